// round 3
// baseline (speedup 1.0000x reference)
#include <cuda_runtime.h>
#include <cstdint>

// VisibilityHeatmap: out[b,k] = in_bounds(coords[b,k]) && heatmaps[b,k,v,u] > 0.4
// coords: [B,K,2] int32 in (u,v) order; heatmaps: [B,K,H,W] f32.
// Output: [B,K] boolean mask materialized as float32 (0.0f / 1.0f).
#define B_DIM 128
#define K_DIM 64
#define H_DIM 128
#define W_DIM 128
#define THRESH 0.4f

__global__ __launch_bounds__(256)
void visibility_kernel(const int2* __restrict__ coords,
                       const float* __restrict__ heatmaps,
                       float* __restrict__ out)
{
    int idx = blockIdx.x * blockDim.x + threadIdx.x;   // idx = b*K + k, 0..8191
    if (idx >= B_DIM * K_DIM) return;

    int2 c = coords[idx];           // c.x = u (W index), c.y = v (H index)
    int u = c.x;
    int v = c.y;

    bool in_bounds = (v > -1) & (u > -1) & (v < H_DIM) & (u < W_DIM);

    int vc = min(max(v, 0), H_DIM - 1);
    int uc = min(max(u, 0), W_DIM - 1);

    // heatmaps[idx, vc, uc] — per-(b,k) plane of H*W floats
    float val = __ldg(&heatmaps[(size_t)idx * (H_DIM * W_DIM) + vc * W_DIM + uc]);

    out[idx] = (in_bounds && (val > THRESH)) ? 1.0f : 0.0f;
}

extern "C" void kernel_launch(void* const* d_in, const int* in_sizes, int n_in,
                              void* d_out, int out_size)
{
    const int2*  coords   = (const int2*)d_in[0];    // [B,K,2] int32
    const float* heatmaps = (const float*)d_in[1];   // [B,K,H,W] f32
    float*       out      = (float*)d_out;           // [B,K] mask as f32

    const int n = B_DIM * K_DIM;                     // 8192
    visibility_kernel<<<(n + 255) / 256, 256>>>(coords, heatmaps, out);
}